// round 2
// baseline (speedup 1.0000x reference)
#include <cuda_runtime.h>
#include <cuda_bf16.h>

// Problem constants
#define B_  8
#define S_  2048
#define H_  1024
#define F_  4096
#define E_  8

// ---------------------------------------------------------------------------
// Device scratch (allocation-free rule: __device__ globals)
// ---------------------------------------------------------------------------
__device__ float g_h   [(long long)B_ * S_ * H_];   //  67 MB  relu(x @ gw1^T)
__device__ float g_u   [(long long)B_ * S_ * F_];   // 268 MB  gelu(x @ mW1^T)
__device__ float g_mW1 [(long long)B_ * F_ * H_];   // 134 MB
__device__ float g_mW2 [(long long)B_ * H_ * F_];   // 134 MB
__device__ float g_mb1 [B_ * F_];
__device__ float g_mb2 [B_ * H_];
__device__ float g_hbar[B_ * H_];
__device__ float g_gate[B_ * E_];

// ---------------------------------------------------------------------------
// Activation helpers
// ---------------------------------------------------------------------------
#define ACT_NONE 0
#define ACT_RELU 1
#define ACT_GELU 2

__device__ __forceinline__ float gelu_tanh(float x) {
    // matches jax.nn.gelu(approximate=True)
    float x3 = x * x * x;
    float y  = 0.7978845608028654f * fmaf(0.044715f, x3, x);
    return 0.5f * x * (1.0f + tanhf(y));
}

template <int ACT>
__device__ __forceinline__ float apply_act(float v) {
    if (ACT == ACT_RELU) return fmaxf(v, 0.0f);
    if (ACT == ACT_GELU) return gelu_tanh(v);
    return v;
}

// ---------------------------------------------------------------------------
// Batched GEMM:  C[b][m,n] = act( sum_k A[b][m,k] * W[b][n,k] + bias[b][n] )
// A: [M,K] row-major, W: [N,K] row-major (K contiguous both sides).
// All of M,N multiples of 128; K multiple of 16. No bounds checks.
// 128x128 block tile, BK=16, 256 threads, 8x8 per-thread, double-buffered.
// ---------------------------------------------------------------------------
#define BM 128
#define BN 128
#define BK 16
#define TM 8
#define TN 8

template <int ACT>
__global__ __launch_bounds__(256, 2)
void gemm_bias_act(const float* __restrict__ Aall, long long sA,
                   const float* __restrict__ Wall, long long sW,
                   const float* __restrict__ biasAll, long long sBias,
                   float* __restrict__ Call, long long sC,
                   int M, int N, int K)
{
    const long long bb = blockIdx.z;
    const float* A    = Aall    + bb * sA;
    const float* W    = Wall    + bb * sW;
    const float* bias = biasAll + bb * sBias;
    float*       C    = Call    + bb * sC;

    __shared__ float As[2][BK][BM];
    __shared__ float Bs[2][BK][BN];

    const int tid = threadIdx.x;
    const int tx  = tid & 15;          // n direction (0..15)
    const int ty  = tid >> 4;          // m direction (0..15)
    const int bm  = blockIdx.y * BM;
    const int bn  = blockIdx.x * BN;

    // loader mapping: 256 threads, each loads 2 float4 from A and 2 from W per tile
    const int lrow = tid >> 2;         // 0..63
    const int lk4  = tid & 3;          // float4 slot along K (covers 16 floats)

    const float* Abase = A + (long long)(bm + lrow) * K + lk4 * 4;
    const float* Wbase = W + (long long)(bn + lrow) * K + lk4 * 4;

    float acc[TM][TN];
    #pragma unroll
    for (int i = 0; i < TM; i++)
        #pragma unroll
        for (int j = 0; j < TN; j++)
            acc[i][j] = 0.0f;

    const int KT = K / BK;

    float4 ra0, ra1, rb0, rb1;

    // prologue: load tile 0
    ra0 = *(const float4*)(Abase);
    ra1 = *(const float4*)(Abase + 64LL * K);
    rb0 = *(const float4*)(Wbase);
    rb1 = *(const float4*)(Wbase + 64LL * K);
    {
        const int kc = lk4 * 4;
        As[0][kc + 0][lrow] = ra0.x;  As[0][kc + 1][lrow] = ra0.y;
        As[0][kc + 2][lrow] = ra0.z;  As[0][kc + 3][lrow] = ra0.w;
        As[0][kc + 0][lrow + 64] = ra1.x;  As[0][kc + 1][lrow + 64] = ra1.y;
        As[0][kc + 2][lrow + 64] = ra1.z;  As[0][kc + 3][lrow + 64] = ra1.w;
        Bs[0][kc + 0][lrow] = rb0.x;  Bs[0][kc + 1][lrow] = rb0.y;
        Bs[0][kc + 2][lrow] = rb0.z;  Bs[0][kc + 3][lrow] = rb0.w;
        Bs[0][kc + 0][lrow + 64] = rb1.x;  Bs[0][kc + 1][lrow + 64] = rb1.y;
        Bs[0][kc + 2][lrow + 64] = rb1.z;  Bs[0][kc + 3][lrow + 64] = rb1.w;
    }
    __syncthreads();

    for (int kt = 0; kt < KT; kt++) {
        const int cur = kt & 1;
        const int nxt = cur ^ 1;

        if (kt + 1 < KT) {
            const long long ko = (long long)(kt + 1) * BK;
            ra0 = *(const float4*)(Abase + ko);
            ra1 = *(const float4*)(Abase + ko + 64LL * K);
            rb0 = *(const float4*)(Wbase + ko);
            rb1 = *(const float4*)(Wbase + ko + 64LL * K);
        }

        #pragma unroll
        for (int kk = 0; kk < BK; kk++) {
            float a[TM], bf[TN];
            *(float4*)&a[0]  = *(const float4*)&As[cur][kk][ty * TM];
            *(float4*)&a[4]  = *(const float4*)&As[cur][kk][ty * TM + 4];
            *(float4*)&bf[0] = *(const float4*)&Bs[cur][kk][tx * TN];
            *(float4*)&bf[4] = *(const float4*)&Bs[cur][kk][tx * TN + 4];
            #pragma unroll
            for (int i = 0; i < TM; i++)
                #pragma unroll
                for (int j = 0; j < TN; j++)
                    acc[i][j] = fmaf(a[i], bf[j], acc[i][j]);
        }

        if (kt + 1 < KT) {
            const int kc = lk4 * 4;
            As[nxt][kc + 0][lrow] = ra0.x;  As[nxt][kc + 1][lrow] = ra0.y;
            As[nxt][kc + 2][lrow] = ra0.z;  As[nxt][kc + 3][lrow] = ra0.w;
            As[nxt][kc + 0][lrow + 64] = ra1.x;  As[nxt][kc + 1][lrow + 64] = ra1.y;
            As[nxt][kc + 2][lrow + 64] = ra1.z;  As[nxt][kc + 3][lrow + 64] = ra1.w;
            Bs[nxt][kc + 0][lrow] = rb0.x;  Bs[nxt][kc + 1][lrow] = rb0.y;
            Bs[nxt][kc + 2][lrow] = rb0.z;  Bs[nxt][kc + 3][lrow] = rb0.w;
            Bs[nxt][kc + 0][lrow + 64] = rb1.x;  Bs[nxt][kc + 1][lrow + 64] = rb1.y;
            Bs[nxt][kc + 2][lrow + 64] = rb1.z;  Bs[nxt][kc + 3][lrow + 64] = rb1.w;
        }
        __syncthreads();
    }

    // epilogue: bias + activation + vectorized store
    float bv[TN];
    *(float4*)&bv[0] = *(const float4*)&bias[bn + tx * TN];
    *(float4*)&bv[4] = *(const float4*)&bias[bn + tx * TN + 4];

    #pragma unroll
    for (int i = 0; i < TM; i++) {
        const long long row = bm + ty * TM + i;
        float* cp = C + row * N + bn + tx * TN;
        float4 o0, o1;
        o0.x = apply_act<ACT>(acc[i][0] + bv[0]);
        o0.y = apply_act<ACT>(acc[i][1] + bv[1]);
        o0.z = apply_act<ACT>(acc[i][2] + bv[2]);
        o0.w = apply_act<ACT>(acc[i][3] + bv[3]);
        o1.x = apply_act<ACT>(acc[i][4] + bv[4]);
        o1.y = apply_act<ACT>(acc[i][5] + bv[5]);
        o1.z = apply_act<ACT>(acc[i][6] + bv[6]);
        o1.w = apply_act<ACT>(acc[i][7] + bv[7]);
        *(float4*)(cp)     = o0;
        *(float4*)(cp + 4) = o1;
    }
}

// ---------------------------------------------------------------------------
// hbar[b][o] = (1/S) * sum_s h[b][s][o]
// ---------------------------------------------------------------------------
__global__ void reduce_hbar_kernel(const float* __restrict__ h, float* __restrict__ hbar)
{
    const int o = blockIdx.x * blockDim.x + threadIdx.x;   // 0..H-1
    const int b = blockIdx.y;
    const float* p = h + (long long)b * S_ * H_ + o;
    float s0 = 0.f, s1 = 0.f, s2 = 0.f, s3 = 0.f;
    #pragma unroll 4
    for (int i = 0; i < S_; i += 4) {
        s0 += p[(long long)(i + 0) * H_];
        s1 += p[(long long)(i + 1) * H_];
        s2 += p[(long long)(i + 2) * H_];
        s3 += p[(long long)(i + 3) * H_];
    }
    hbar[b * H_ + o] = (s0 + s1 + s2 + s3) * (1.0f / S_);
}

// ---------------------------------------------------------------------------
// g[b][e] = hbar[b] . gw2[e] + gb2[e]
// ---------------------------------------------------------------------------
__global__ void gate_g_kernel(const float* __restrict__ hbar,
                              const float* __restrict__ w2,
                              const float* __restrict__ b2,
                              float* __restrict__ g)
{
    const int e = blockIdx.x;
    const int b = blockIdx.y;
    float s = 0.f;
    for (int o = threadIdx.x; o < H_; o += 128)
        s += hbar[b * H_ + o] * w2[e * H_ + o];
    __shared__ float red[128];
    red[threadIdx.x] = s;
    __syncthreads();
    for (int st = 64; st > 0; st >>= 1) {
        if (threadIdx.x < st) red[threadIdx.x] += red[threadIdx.x + st];
        __syncthreads();
    }
    if (threadIdx.x == 0) g[b * E_ + e] = red[0] + b2[e];
}

// ---------------------------------------------------------------------------
// mW[b] = Wbase + sum_e g[b][e] * T[e]   (flattened, float4-vectorized)
// n4 = (#floats)/4 of one weight matrix. Reads T exactly once for all 8 samples.
// ---------------------------------------------------------------------------
__global__ void merge_w_kernel(const float4* __restrict__ Wbase,
                               const float4* __restrict__ T,
                               const float*  __restrict__ g,
                               float4* __restrict__ out, int n4)
{
    __shared__ float sg[B_ * E_];
    if (threadIdx.x < B_ * E_) sg[threadIdx.x] = g[threadIdx.x];
    __syncthreads();

    const int i = blockIdx.x * blockDim.x + threadIdx.x;
    if (i >= n4) return;

    const float4 w = Wbase[i];
    float4 tv[E_];
    #pragma unroll
    for (int e = 0; e < E_; e++) tv[e] = T[(long long)e * n4 + i];

    #pragma unroll
    for (int b = 0; b < B_; b++) {
        float4 a = w;
        #pragma unroll
        for (int e = 0; e < E_; e++) {
            const float ge = sg[b * E_ + e];
            a.x = fmaf(ge, tv[e].x, a.x);
            a.y = fmaf(ge, tv[e].y, a.y);
            a.z = fmaf(ge, tv[e].z, a.z);
            a.w = fmaf(ge, tv[e].w, a.w);
        }
        out[(long long)b * n4 + i] = a;
    }
}

// ---------------------------------------------------------------------------
// mb[b][i] = base[i] + sum_e g[b][e] * T[e][i]
// ---------------------------------------------------------------------------
__global__ void merge_bias_kernel(const float* __restrict__ base,
                                  const float* __restrict__ T,
                                  const float* __restrict__ g,
                                  float* __restrict__ out, int n)
{
    const int i = blockIdx.x * blockDim.x + threadIdx.x;
    if (i >= n) return;
    const float w = base[i];
    float tv[E_];
    #pragma unroll
    for (int e = 0; e < E_; e++) tv[e] = T[e * n + i];
    #pragma unroll
    for (int b = 0; b < B_; b++) {
        float a = w;
        #pragma unroll
        for (int e = 0; e < E_; e++) a = fmaf(g[b * E_ + e], tv[e], a);
        out[b * n + i] = a;
    }
}

// ---------------------------------------------------------------------------
// Launch
// ---------------------------------------------------------------------------
extern "C" void kernel_launch(void* const* d_in, const int* in_sizes, int n_in,
                              void* d_out, int out_size)
{
    const float* x   = (const float*)d_in[0];   // [B,S,H]
    const float* gw1 = (const float*)d_in[1];   // [H,H]
    const float* gb1 = (const float*)d_in[2];   // [H]
    const float* gw2 = (const float*)d_in[3];   // [E,H]
    const float* gb2 = (const float*)d_in[4];   // [E]
    const float* W1  = (const float*)d_in[5];   // [F,H]
    const float* b1  = (const float*)d_in[6];   // [F]
    const float* W2  = (const float*)d_in[7];   // [H,F]
    const float* b2  = (const float*)d_in[8];   // [H]
    const float* TW1 = (const float*)d_in[9];   // [E,F,H]
    const float* Tb1 = (const float*)d_in[10];  // [E,F]
    const float* TW2 = (const float*)d_in[11];  // [E,H,F]
    const float* Tb2 = (const float*)d_in[12];  // [E,H]
    float* out = (float*)d_out;                 // [B,S,H]

    float *h, *u, *mW1, *mW2, *mb1, *mb2, *hbar, *g;
    cudaGetSymbolAddress((void**)&h,    g_h);
    cudaGetSymbolAddress((void**)&u,    g_u);
    cudaGetSymbolAddress((void**)&mW1,  g_mW1);
    cudaGetSymbolAddress((void**)&mW2,  g_mW2);
    cudaGetSymbolAddress((void**)&mb1,  g_mb1);
    cudaGetSymbolAddress((void**)&mb2,  g_mb2);
    cudaGetSymbolAddress((void**)&hbar, g_hbar);
    cudaGetSymbolAddress((void**)&g,    g_gate);

    // 1) Gate hidden: h = relu(x @ gw1^T + gb1), flattened [B*S, H] x [H, H]
    gemm_bias_act<ACT_RELU><<<dim3(H_ / BN, (B_ * S_) / BM, 1), 256>>>(
        x, 0, gw1, 0, gb1, 0, h, 0, B_ * S_, H_, H_);

    // 2) hbar = mean_s(h);   g = hbar @ gw2^T + gb2
    reduce_hbar_kernel<<<dim3(H_ / 256, B_), 256>>>(h, hbar);
    gate_g_kernel<<<dim3(E_, B_), 128>>>(hbar, gw2, gb2, g);

    // 3) Per-sample merged weights & biases
    const int n4w = (F_ * H_) / 4;  // same count for both weight matrices
    merge_w_kernel<<<(n4w + 255) / 256, 256>>>(
        (const float4*)W1, (const float4*)TW1, g, (float4*)mW1, n4w);
    merge_w_kernel<<<(n4w + 255) / 256, 256>>>(
        (const float4*)W2, (const float4*)TW2, g, (float4*)mW2, n4w);
    merge_bias_kernel<<<(F_ + 255) / 256, 256>>>(b1, Tb1, g, mb1, F_);
    merge_bias_kernel<<<(H_ + 255) / 256, 256>>>(b2, Tb2, g, mb2, H_);

    // 4) FFN1: u[b] = gelu(x[b] @ mW1[b]^T + mb1[b])   [S,H]x[F,H] -> [S,F]
    gemm_bias_act<ACT_GELU><<<dim3(F_ / BN, S_ / BM, B_), 256>>>(
        x, (long long)S_ * H_, mW1, (long long)F_ * H_, mb1, F_,
        u, (long long)S_ * F_, S_, F_, H_);

    // 5) FFN2: out[b] = u[b] @ mW2[b]^T + mb2[b]       [S,F]x[H,F] -> [S,H]
    gemm_bias_act<ACT_NONE><<<dim3(H_ / BN, S_ / BM, B_), 256>>>(
        u, (long long)S_ * F_, mW2, (long long)H_ * F_, mb2, H_,
        out, (long long)S_ * H_, S_, H_, F_);
}

// round 4
// speedup vs baseline: 1.8541x; 1.8541x over previous
#include <cuda_runtime.h>
#include <cuda_bf16.h>
#include <cstdint>

// Problem constants
#define B_  8
#define S_  2048
#define H_  1024
#define F_  4096
#define E_  8

// ---------------------------------------------------------------------------
// Device scratch (allocation-free rule: __device__ globals). bf16 arrays are
// declared as uint4 so the base is 16B-aligned for cp.async / vector stores.
// ---------------------------------------------------------------------------
__device__ float g_h   [(long long)B_ * S_ * H_];            // 67 MB fp32 gate hidden
__device__ uint4 g_xhi [(long long)B_ * S_ * H_ / 8];        // 33.5 MB bf16
__device__ uint4 g_xlo [(long long)B_ * S_ * H_ / 8];
__device__ uint4 g_gwhi[(long long)H_ * H_ / 8];
__device__ uint4 g_gwlo[(long long)H_ * H_ / 8];
__device__ uint4 g_mW1hi[(long long)B_ * F_ * H_ / 8];       // 67 MB each
__device__ uint4 g_mW1lo[(long long)B_ * F_ * H_ / 8];
__device__ uint4 g_mW2hi[(long long)B_ * H_ * F_ / 8];
__device__ uint4 g_mW2lo[(long long)B_ * H_ * F_ / 8];
__device__ uint4 g_uhi [(long long)B_ * S_ * F_ / 8];        // 134 MB each
__device__ uint4 g_ulo [(long long)B_ * S_ * F_ / 8];
__device__ float g_mb1 [B_ * F_];
__device__ float g_mb2 [B_ * H_];
__device__ float g_hbar[B_ * H_];
__device__ float g_gate[B_ * E_];

// ---------------------------------------------------------------------------
// Activation
// ---------------------------------------------------------------------------
#define ACT_NONE 0
#define ACT_RELU 1
#define ACT_GELU 2

__device__ __forceinline__ float gelu_tanh(float x) {
    float x3 = x * x * x;
    float y  = 0.7978845608028654f * fmaf(0.044715f, x3, x);
    return 0.5f * x * (1.0f + tanhf(y));
}
template <int ACT>
__device__ __forceinline__ float apply_act(float v) {
    if (ACT == ACT_RELU) return fmaxf(v, 0.0f);
    if (ACT == ACT_GELU) return gelu_tanh(v);
    return v;
}

// ---------------------------------------------------------------------------
// PTX helpers
// ---------------------------------------------------------------------------
__device__ __forceinline__ uint32_t smem_u32(const void* p) {
    return static_cast<uint32_t>(__cvta_generic_to_shared(p));
}
__device__ __forceinline__ void cp16(void* sdst, const void* gsrc) {
    asm volatile("cp.async.cg.shared.global [%0], [%1], 16;\n"
                 :: "r"(smem_u32(sdst)), "l"(gsrc));
}
__device__ __forceinline__ void cp_commit() {
    asm volatile("cp.async.commit_group;\n");
}
template <int N>
__device__ __forceinline__ void cp_wait() {
    asm volatile("cp.async.wait_group %0;\n" :: "n"(N));
}
__device__ __forceinline__ void ldsm_x4(uint32_t r[4], uint32_t addr) {
    asm volatile("ldmatrix.sync.aligned.m8n8.x4.shared.b16 {%0,%1,%2,%3}, [%4];\n"
                 : "=r"(r[0]), "=r"(r[1]), "=r"(r[2]), "=r"(r[3]) : "r"(addr));
}
__device__ __forceinline__ void mma_bf16(float c[4], const uint32_t a[4], const uint32_t b[2]) {
    asm volatile("mma.sync.aligned.m16n8k16.row.col.f32.bf16.bf16.f32 "
                 "{%0,%1,%2,%3}, {%4,%5,%6,%7}, {%8,%9}, {%0,%1,%2,%3};\n"
                 : "+f"(c[0]), "+f"(c[1]), "+f"(c[2]), "+f"(c[3])
                 : "r"(a[0]), "r"(a[1]), "r"(a[2]), "r"(a[3]), "r"(b[0]), "r"(b[1]));
}

// ---------------------------------------------------------------------------
// Tensor-core batched GEMM with fp32->bf16 hi/lo split (3-product scheme):
//   C[b][m,n] = act( sum_k A[b][m,k]*W[b][n,k] + bias[b][n] )
// A,W provided as pre-split bf16 hi/lo, K contiguous. M,N mult of 128, K of 16.
// Block 128x128, BK=16, 8 warps (2x4), warp tile 64x32, cp.async 2-stage.
// ---------------------------------------------------------------------------
#define BM 128
#define BN 128
#define BKh 16
#define PAD 8
#define LDS_ (BKh + PAD)   // 24 halves = 48 B row stride (conflict-free ldmatrix)

template <int ACT, bool SPLIT_OUT>
__global__ __launch_bounds__(256, 1)
void gemm_mma(const __nv_bfloat16* __restrict__ Ahi, const __nv_bfloat16* __restrict__ Alo,
              long long sA,
              const __nv_bfloat16* __restrict__ Whi, const __nv_bfloat16* __restrict__ Wlo,
              long long sW,
              const float* __restrict__ biasAll, long long sBias,
              float* __restrict__ Cf, __nv_bfloat16* __restrict__ Chi,
              __nv_bfloat16* __restrict__ Clo, long long sC,
              int M, int N, int K)
{
    __shared__ __align__(16) __nv_bfloat16 s_ahi[2][BM][LDS_];
    __shared__ __align__(16) __nv_bfloat16 s_alo[2][BM][LDS_];
    __shared__ __align__(16) __nv_bfloat16 s_bhi[2][BN][LDS_];
    __shared__ __align__(16) __nv_bfloat16 s_blo[2][BN][LDS_];

    const int  tid  = threadIdx.x;
    const int  lane = tid & 31;
    const int  wid  = tid >> 5;
    const int  wm   = wid >> 2;          // 0..1
    const int  wn   = wid & 3;           // 0..3
    const int  bm   = blockIdx.y * BM;
    const int  bn   = blockIdx.x * BN;
    const long long bb = blockIdx.z;

    const __nv_bfloat16* Ah = Ahi + bb * sA;
    const __nv_bfloat16* Al = Alo + bb * sA;
    const __nv_bfloat16* Wh = Whi + bb * sW;
    const __nv_bfloat16* Wl = Wlo + bb * sW;
    const float* bias = biasAll + bb * sBias;

    // loader mapping: 256 threads; per tile each thread does one 16B cp.async
    const int lr  = tid >> 1;       // 0..127 row
    const int ls  = (tid & 1) * 8;  // halves offset within k-slab

    float acc[4][4][4];
    #pragma unroll
    for (int i = 0; i < 4; i++)
        #pragma unroll
        for (int j = 0; j < 4; j++)
            #pragma unroll
            for (int c = 0; c < 4; c++) acc[i][j][c] = 0.0f;

    const int KT = K / BKh;

    // prologue: stage 0
    {
        const long long k0 = 0;
        cp16(&s_ahi[0][lr][ls], Ah + (long long)(bm + lr) * K + k0 + ls);
        cp16(&s_alo[0][lr][ls], Al + (long long)(bm + lr) * K + k0 + ls);
        cp16(&s_bhi[0][lr][ls], Wh + (long long)(bn + lr) * K + k0 + ls);
        cp16(&s_blo[0][lr][ls], Wl + (long long)(bn + lr) * K + k0 + ls);
        cp_commit();
    }

    for (int kt = 0; kt < KT; kt++) {
        const int cur = kt & 1;
        if (kt + 1 < KT) {
            const int nxt = cur ^ 1;
            const long long k0 = (long long)(kt + 1) * BKh;
            cp16(&s_ahi[nxt][lr][ls], Ah + (long long)(bm + lr) * K + k0 + ls);
            cp16(&s_alo[nxt][lr][ls], Al + (long long)(bm + lr) * K + k0 + ls);
            cp16(&s_bhi[nxt][lr][ls], Wh + (long long)(bn + lr) * K + k0 + ls);
            cp16(&s_blo[nxt][lr][ls], Wl + (long long)(bn + lr) * K + k0 + ls);
            cp_commit();
            cp_wait<1>();
        } else {
            cp_wait<0>();
        }
        __syncthreads();

        // fragment loads
        uint32_t ahi[4][4], alo[4][4];
        uint32_t bhi[4][2], blo[4][2];
        const int frow = lane & 15;
        const int fcol = (lane >> 4) * 8;
        #pragma unroll
        for (int mi = 0; mi < 4; mi++) {
            const int r = wm * 64 + mi * 16 + frow;
            ldsm_x4(ahi[mi], smem_u32(&s_ahi[cur][r][fcol]));
            ldsm_x4(alo[mi], smem_u32(&s_alo[cur][r][fcol]));
        }
        #pragma unroll
        for (int nj2 = 0; nj2 < 2; nj2++) {
            const int r = wn * 32 + nj2 * 16 + frow;
            uint32_t t[4];
            ldsm_x4(t, smem_u32(&s_bhi[cur][r][fcol]));
            bhi[nj2*2+0][0] = t[0]; bhi[nj2*2+0][1] = t[2];
            bhi[nj2*2+1][0] = t[1]; bhi[nj2*2+1][1] = t[3];
            ldsm_x4(t, smem_u32(&s_blo[cur][r][fcol]));
            blo[nj2*2+0][0] = t[0]; blo[nj2*2+0][1] = t[2];
            blo[nj2*2+1][0] = t[1]; blo[nj2*2+1][1] = t[3];
        }

        #pragma unroll
        for (int mi = 0; mi < 4; mi++)
            #pragma unroll
            for (int nj = 0; nj < 4; nj++) {
                mma_bf16(acc[mi][nj], ahi[mi], bhi[nj]);   // hi*hi
                mma_bf16(acc[mi][nj], ahi[mi], blo[nj]);   // hi*lo
                mma_bf16(acc[mi][nj], alo[mi], bhi[nj]);   // lo*hi
            }
        __syncthreads();
    }

    // epilogue
    #pragma unroll
    for (int mi = 0; mi < 4; mi++) {
        #pragma unroll
        for (int nj = 0; nj < 4; nj++) {
            const int m0 = bm + wm * 64 + mi * 16 + (lane >> 2);
            const int n0 = bn + wn * 32 + nj * 8 + (lane & 3) * 2;
            const float b0 = bias[n0], b1v = bias[n0 + 1];
            float v00 = apply_act<ACT>(acc[mi][nj][0] + b0);
            float v01 = apply_act<ACT>(acc[mi][nj][1] + b1v);
            float v10 = apply_act<ACT>(acc[mi][nj][2] + b0);
            float v11 = apply_act<ACT>(acc[mi][nj][3] + b1v);
            if (SPLIT_OUT) {
                __nv_bfloat16 h00 = __float2bfloat16_rn(v00);
                __nv_bfloat16 h01 = __float2bfloat16_rn(v01);
                __nv_bfloat16 h10 = __float2bfloat16_rn(v10);
                __nv_bfloat16 h11 = __float2bfloat16_rn(v11);
                __nv_bfloat162 hp0{h00, h01}, hp1{h10, h11};
                __nv_bfloat162 lp0{__float2bfloat16_rn(v00 - __bfloat162float(h00)),
                                   __float2bfloat16_rn(v01 - __bfloat162float(h01))};
                __nv_bfloat162 lp1{__float2bfloat16_rn(v10 - __bfloat162float(h10)),
                                   __float2bfloat16_rn(v11 - __bfloat162float(h11))};
                __nv_bfloat16* ph = Chi + bb * sC;
                __nv_bfloat16* pl = Clo + bb * sC;
                *(__nv_bfloat162*)(ph + (long long)m0 * N + n0)       = hp0;
                *(__nv_bfloat162*)(ph + (long long)(m0 + 8) * N + n0) = hp1;
                *(__nv_bfloat162*)(pl + (long long)m0 * N + n0)       = lp0;
                *(__nv_bfloat162*)(pl + (long long)(m0 + 8) * N + n0) = lp1;
            } else {
                float* pc = Cf + bb * sC;
                *(float2*)(pc + (long long)m0 * N + n0)       = make_float2(v00, v01);
                *(float2*)(pc + (long long)(m0 + 8) * N + n0) = make_float2(v10, v11);
            }
        }
    }
}

// ---------------------------------------------------------------------------
// fp32 -> (bf16 hi, bf16 lo) split, 4 floats/thread
// ---------------------------------------------------------------------------
__global__ void split_f32_kernel(const float4* __restrict__ in,
                                 uint2* __restrict__ hi, uint2* __restrict__ lo, int n4)
{
    const int i = blockIdx.x * blockDim.x + threadIdx.x;
    if (i >= n4) return;
    const float4 v = in[i];
    __nv_bfloat16 hx = __float2bfloat16_rn(v.x), hy = __float2bfloat16_rn(v.y);
    __nv_bfloat16 hz = __float2bfloat16_rn(v.z), hw = __float2bfloat16_rn(v.w);
    __nv_bfloat162 hp0{hx, hy}, hp1{hz, hw};
    __nv_bfloat162 lp0{__float2bfloat16_rn(v.x - __bfloat162float(hx)),
                       __float2bfloat16_rn(v.y - __bfloat162float(hy))};
    __nv_bfloat162 lp1{__float2bfloat16_rn(v.z - __bfloat162float(hz)),
                       __float2bfloat16_rn(v.w - __bfloat162float(hw))};
    uint2 ho, loo;
    ho.x  = *(const uint32_t*)&hp0;  ho.y  = *(const uint32_t*)&hp1;
    loo.x = *(const uint32_t*)&lp0;  loo.y = *(const uint32_t*)&lp1;
    hi[i] = ho;  lo[i] = loo;
}

// ---------------------------------------------------------------------------
// hbar[b][o] = (1/S) * sum_s h[b][s][o]
// ---------------------------------------------------------------------------
__global__ void reduce_hbar_kernel(const float* __restrict__ h, float* __restrict__ hbar)
{
    const int o = blockIdx.x * blockDim.x + threadIdx.x;
    const int b = blockIdx.y;
    const float* p = h + (long long)b * S_ * H_ + o;
    float s0 = 0.f, s1 = 0.f, s2 = 0.f, s3 = 0.f;
    #pragma unroll 4
    for (int i = 0; i < S_; i += 4) {
        s0 += p[(long long)(i + 0) * H_];
        s1 += p[(long long)(i + 1) * H_];
        s2 += p[(long long)(i + 2) * H_];
        s3 += p[(long long)(i + 3) * H_];
    }
    hbar[b * H_ + o] = (s0 + s1 + s2 + s3) * (1.0f / S_);
}

// ---------------------------------------------------------------------------
// g[b][e] = hbar[b] . gw2[e] + gb2[e]
// ---------------------------------------------------------------------------
__global__ void gate_g_kernel(const float* __restrict__ hbar,
                              const float* __restrict__ w2,
                              const float* __restrict__ b2,
                              float* __restrict__ g)
{
    const int e = blockIdx.x;
    const int b = blockIdx.y;
    float s = 0.f;
    for (int o = threadIdx.x; o < H_; o += 128)
        s += hbar[b * H_ + o] * w2[e * H_ + o];
    __shared__ float red[128];
    red[threadIdx.x] = s;
    __syncthreads();
    for (int st = 64; st > 0; st >>= 1) {
        if (threadIdx.x < st) red[threadIdx.x] += red[threadIdx.x + st];
        __syncthreads();
    }
    if (threadIdx.x == 0) g[b * E_ + e] = red[0] + b2[e];
}

// ---------------------------------------------------------------------------
// mW[b] = Wbase + sum_e g[b][e]*T[e], written directly as bf16 hi/lo
// ---------------------------------------------------------------------------
__global__ void merge_w_split_kernel(const float4* __restrict__ Wbase,
                                     const float4* __restrict__ T,
                                     const float*  __restrict__ g,
                                     uint2* __restrict__ hi, uint2* __restrict__ lo,
                                     int n4)
{
    __shared__ float sg[B_ * E_];
    if (threadIdx.x < B_ * E_) sg[threadIdx.x] = g[threadIdx.x];
    __syncthreads();

    const int i = blockIdx.x * blockDim.x + threadIdx.x;
    if (i >= n4) return;

    const float4 w = Wbase[i];
    float4 tv[E_];
    #pragma unroll
    for (int e = 0; e < E_; e++) tv[e] = T[(long long)e * n4 + i];

    #pragma unroll
    for (int b = 0; b < B_; b++) {
        float4 a = w;
        #pragma unroll
        for (int e = 0; e < E_; e++) {
            const float ge = sg[b * E_ + e];
            a.x = fmaf(ge, tv[e].x, a.x);
            a.y = fmaf(ge, tv[e].y, a.y);
            a.z = fmaf(ge, tv[e].z, a.z);
            a.w = fmaf(ge, tv[e].w, a.w);
        }
        __nv_bfloat16 hx = __float2bfloat16_rn(a.x), hy = __float2bfloat16_rn(a.y);
        __nv_bfloat16 hz = __float2bfloat16_rn(a.z), hw = __float2bfloat16_rn(a.w);
        __nv_bfloat162 hp0{hx, hy}, hp1{hz, hw};
        __nv_bfloat162 lp0{__float2bfloat16_rn(a.x - __bfloat162float(hx)),
                           __float2bfloat16_rn(a.y - __bfloat162float(hy))};
        __nv_bfloat162 lp1{__float2bfloat16_rn(a.z - __bfloat162float(hz)),
                           __float2bfloat16_rn(a.w - __bfloat162float(hw))};
        uint2 ho, loo;
        ho.x  = *(const uint32_t*)&hp0;  ho.y  = *(const uint32_t*)&hp1;
        loo.x = *(const uint32_t*)&lp0;  loo.y = *(const uint32_t*)&lp1;
        hi[(long long)b * n4 + i] = ho;
        lo[(long long)b * n4 + i] = loo;
    }
}

// ---------------------------------------------------------------------------
// mb[b][i] = base[i] + sum_e g[b][e]*T[e][i]  (fp32)
// ---------------------------------------------------------------------------
__global__ void merge_bias_kernel(const float* __restrict__ base,
                                  const float* __restrict__ T,
                                  const float* __restrict__ g,
                                  float* __restrict__ out, int n)
{
    const int i = blockIdx.x * blockDim.x + threadIdx.x;
    if (i >= n) return;
    const float w = base[i];
    float tv[E_];
    #pragma unroll
    for (int e = 0; e < E_; e++) tv[e] = T[e * n + i];
    #pragma unroll
    for (int b = 0; b < B_; b++) {
        float a = w;
        #pragma unroll
        for (int e = 0; e < E_; e++) a = fmaf(g[b * E_ + e], tv[e], a);
        out[b * n + i] = a;
    }
}

// ---------------------------------------------------------------------------
// Launch
// ---------------------------------------------------------------------------
extern "C" void kernel_launch(void* const* d_in, const int* in_sizes, int n_in,
                              void* d_out, int out_size)
{
    const float* x   = (const float*)d_in[0];   // [B,S,H]
    const float* gw1 = (const float*)d_in[1];   // [H,H]
    const float* gb1 = (const float*)d_in[2];   // [H]
    const float* gw2 = (const float*)d_in[3];   // [E,H]
    const float* gb2 = (const float*)d_in[4];   // [E]
    const float* W1  = (const float*)d_in[5];   // [F,H]
    const float* b1  = (const float*)d_in[6];   // [F]
    const float* W2  = (const float*)d_in[7];   // [H,F]
    const float* b2  = (const float*)d_in[8];   // [H]
    const float* TW1 = (const float*)d_in[9];   // [E,F,H]
    const float* Tb1 = (const float*)d_in[10];  // [E,F]
    const float* TW2 = (const float*)d_in[11];  // [E,H,F]
    const float* Tb2 = (const float*)d_in[12];  // [E,H]
    float* out = (float*)d_out;                 // [B,S,H]

    float *h, *mb1, *mb2, *hbar, *g;
    void *xhi, *xlo, *gwhi, *gwlo, *mW1hi, *mW1lo, *mW2hi, *mW2lo, *uhi, *ulo;
    cudaGetSymbolAddress((void**)&h,    g_h);
    cudaGetSymbolAddress(&xhi,   g_xhi);   cudaGetSymbolAddress(&xlo,   g_xlo);
    cudaGetSymbolAddress(&gwhi,  g_gwhi);  cudaGetSymbolAddress(&gwlo,  g_gwlo);
    cudaGetSymbolAddress(&mW1hi, g_mW1hi); cudaGetSymbolAddress(&mW1lo, g_mW1lo);
    cudaGetSymbolAddress(&mW2hi, g_mW2hi); cudaGetSymbolAddress(&mW2lo, g_mW2lo);
    cudaGetSymbolAddress(&uhi,   g_uhi);   cudaGetSymbolAddress(&ulo,   g_ulo);
    cudaGetSymbolAddress((void**)&mb1,  g_mb1);
    cudaGetSymbolAddress((void**)&mb2,  g_mb2);
    cudaGetSymbolAddress((void**)&hbar, g_hbar);
    cudaGetSymbolAddress((void**)&g,    g_gate);

    const int M  = B_ * S_;                    // 16384

    // 0) split x and gate w1 into bf16 hi/lo
    {
        const int n4 = M * H_ / 4;
        split_f32_kernel<<<(n4 + 255) / 256, 256>>>(
            (const float4*)x, (uint2*)xhi, (uint2*)xlo, n4);
        const int n4g = H_ * H_ / 4;
        split_f32_kernel<<<(n4g + 255) / 256, 256>>>(
            (const float4*)gw1, (uint2*)gwhi, (uint2*)gwlo, n4g);
    }

    // 1) gate hidden: h = relu(x @ gw1^T + gb1)  [16384,1024] x [1024,1024]
    gemm_mma<ACT_RELU, false><<<dim3(H_ / BN, M / BM, 1), 256>>>(
        (const __nv_bfloat16*)xhi, (const __nv_bfloat16*)xlo, 0,
        (const __nv_bfloat16*)gwhi, (const __nv_bfloat16*)gwlo, 0,
        gb1, 0, h, nullptr, nullptr, 0, M, H_, H_);

    // 2) hbar = mean_s(h);  g = hbar @ gw2^T + gb2
    reduce_hbar_kernel<<<dim3(H_ / 256, B_), 256>>>(h, hbar);
    gate_g_kernel<<<dim3(E_, B_), 128>>>(hbar, gw2, gb2, g);

    // 3) merged weights (split to bf16 hi/lo) + biases
    const int n4w = (F_ * H_) / 4;
    merge_w_split_kernel<<<(n4w + 255) / 256, 256>>>(
        (const float4*)W1, (const float4*)TW1, g, (uint2*)mW1hi, (uint2*)mW1lo, n4w);
    merge_w_split_kernel<<<(n4w + 255) / 256, 256>>>(
        (const float4*)W2, (const float4*)TW2, g, (uint2*)mW2hi, (uint2*)mW2lo, n4w);
    merge_bias_kernel<<<(F_ + 255) / 256, 256>>>(b1, Tb1, g, mb1, F_);
    merge_bias_kernel<<<(H_ + 255) / 256, 256>>>(b2, Tb2, g, mb2, H_);

    // 4) FFN1: u = gelu(x @ mW1^T + mb1) -> bf16 hi/lo   [2048,1024]x[4096,1024]
    gemm_mma<ACT_GELU, true><<<dim3(F_ / BN, S_ / BM, B_), 256>>>(
        (const __nv_bfloat16*)xhi, (const __nv_bfloat16*)xlo, (long long)S_ * H_,
        (const __nv_bfloat16*)mW1hi, (const __nv_bfloat16*)mW1lo, (long long)F_ * H_,
        mb1, F_, nullptr, (__nv_bfloat16*)uhi, (__nv_bfloat16*)ulo, (long long)S_ * F_,
        S_, F_, H_);

    // 5) FFN2: out = u @ mW2^T + mb2   [2048,4096]x[1024,4096] -> fp32
    gemm_mma<ACT_NONE, false><<<dim3(H_ / BN, S_ / BM, B_), 256>>>(
        (const __nv_bfloat16*)uhi, (const __nv_bfloat16*)ulo, (long long)S_ * F_,
        (const __nv_bfloat16*)mW2hi, (const __nv_bfloat16*)mW2lo, (long long)H_ * F_,
        mb2, H_, out, nullptr, nullptr, (long long)S_ * H_,
        S_, H_, F_);
}